// round 13
// baseline (speedup 1.0000x reference)
#include <cuda_runtime.h>
#include <cuda_bf16.h>
#include <mma.h>
#include <math.h>

using namespace nvcuda;

// Problem constants (fixed by the dataset)
#define NROWS 20000
#define INF   1024
#define OUTF  64

// ---------------------------------------------------------------------------
// Scratch (device globals; no runtime allocation allowed)
// ---------------------------------------------------------------------------
__device__ alignas(256) float g_z0 [NROWS * OUTF];          // feat   @ W1
__device__ alignas(256) float g_za0[20064 * OUTF];          // feat_a @ W1 (padded: gemm1 tail rows)
__device__ alignas(256) float g_z2 [NROWS * OUTF];          // spmm(A, z)
__device__ alignas(256) float g_sa [NROWS * OUTF];          // spmm(A,  za0)
__device__ alignas(256) float g_ss [NROWS * OUTF];          // spmm(Aa, za0)

// ---------------------------------------------------------------------------
// fp32 -> bf16 hi/lo split helpers (error-compensated tensor-core GEMM)
// ---------------------------------------------------------------------------
__device__ __forceinline__ void split_store2(__nv_bfloat16* hiPtr, __nv_bfloat16* loPtr,
                                             float x, float y) {
    __nv_bfloat162 h = __floats2bfloat162_rn(x, y);
    *reinterpret_cast<__nv_bfloat162*>(hiPtr) = h;
    float rx = x - __bfloat162float(__low2bfloat16(h));
    float ry = y - __bfloat162float(__high2bfloat16(h));
    *reinterpret_cast<__nv_bfloat162*>(loPtr) = __floats2bfloat162_rn(rx, ry);
}

__device__ __forceinline__ void split_store_f4(__nv_bfloat16* hi, __nv_bfloat16* lo, float4 v) {
    split_store2(hi + 0, lo + 0, v.x, v.y);
    split_store2(hi + 2, lo + 2, v.z, v.w);
}

// ---------------------------------------------------------------------------
// zero scratch that receives atomic scatter (+ z region of d_out)
// ---------------------------------------------------------------------------
__global__ void __launch_bounds__(256) zero_kernel(float* __restrict__ z_out) {
    int i = blockIdx.x * 256 + threadIdx.x;            // over 320000 float4 per array
    if (i < (NROWS * OUTF) / 4) {
        float4 z = make_float4(0.f, 0.f, 0.f, 0.f);
        reinterpret_cast<float4*>(z_out)[i] = z;
        reinterpret_cast<float4*>(g_sa)[i]  = z;
        reinterpret_cast<float4*>(g_ss)[i]  = z;
        reinterpret_cast<float4*>(g_z2)[i]  = z;
    }
}

// ---------------------------------------------------------------------------
// GEMM1: [40000,1024] @ [1024,64] -> z0 / za0
// BM=128, BN=64, BK=32, 8 warps, warp tile 32x32, bf16x3 split MMA.
// Double-buffered smem + register prefetch: one __syncthreads per K-iter,
// next tile's LDGs issued before the current tile's MMAs.
// Dynamic smem: 2 stages x (A 128x48 hi/lo + B 32x80 hi/lo) = 69632 B.
// ---------------------------------------------------------------------------
#define G1_STAGE_ELEMS (128*48*2 + 32*80*2)   // 17408 bf16 per stage

__global__ void __launch_bounds__(256) gemm1_kernel(const float* __restrict__ feat,
                                                    const float* __restrict__ feat_a,
                                                    const float* __restrict__ W1) {
    extern __shared__ __nv_bfloat16 smem1[];

    const int tid  = threadIdx.x;
    const int warp = tid >> 5;
    const int wm   = warp & 3;   // 4 row groups of 32
    const int wn   = warp >> 2;  // 2 col groups of 32
    const int bm0  = blockIdx.x * 128;

    wmma::fragment<wmma::accumulator, 16, 16, 16, float> acc[2][2];
#pragma unroll
    for (int i = 0; i < 2; i++)
#pragma unroll
        for (int j = 0; j < 2; j++) wmma::fill_fragment(acc[i][j], 0.0f);

    float4 aReg[4];
    float4 bReg[2];

    auto prefetch = [&](int k0) {
#pragma unroll
        for (int it = 0; it < 4; it++) {
            int idx = tid + it * 256;          // 0..1023
            int r   = idx >> 3;                // 0..127
            int c   = (idx & 7) * 4;           // 0..28
            int gr  = bm0 + r;
            float4 v = make_float4(0.f, 0.f, 0.f, 0.f);
            if (gr < 2 * NROWS) {
                const float* src = (gr < NROWS) ? (feat + (size_t)gr * INF)
                                                : (feat_a + (size_t)(gr - NROWS) * INF);
                v = *reinterpret_cast<const float4*>(src + k0 + c);
            }
            aReg[it] = v;
        }
#pragma unroll
        for (int it = 0; it < 2; it++) {
            int idx = tid + it * 256;          // 0..511
            int r   = idx >> 4;                // 0..31
            int c   = (idx & 15) * 4;          // 0..60
            bReg[it] = *reinterpret_cast<const float4*>(W1 + (size_t)(k0 + r) * OUTF + c);
        }
    };

    auto storeStage = [&](int s) {
        __nv_bfloat16* Ah = smem1 + s * G1_STAGE_ELEMS;
        __nv_bfloat16* Al = Ah + 128 * 48;
        __nv_bfloat16* Bh = Al + 128 * 48;
        __nv_bfloat16* Bl = Bh + 32 * 80;
#pragma unroll
        for (int it = 0; it < 4; it++) {
            int idx = tid + it * 256;
            int r   = idx >> 3;
            int c   = (idx & 7) * 4;
            split_store_f4(Ah + r * 48 + c, Al + r * 48 + c, aReg[it]);
        }
#pragma unroll
        for (int it = 0; it < 2; it++) {
            int idx = tid + it * 256;
            int r   = idx >> 4;
            int c   = (idx & 15) * 4;
            split_store_f4(Bh + r * 80 + c, Bl + r * 80 + c, bReg[it]);
        }
    };

    prefetch(0);
    storeStage(0);
    __syncthreads();

#pragma unroll 1
    for (int it = 0; it < 32; it++) {
        const int cur = it & 1;
        if (it < 31) prefetch((it + 1) * 32);   // long-latency LDGs issued first

        const __nv_bfloat16* Ah = smem1 + cur * G1_STAGE_ELEMS;
        const __nv_bfloat16* Al = Ah + 128 * 48;
        const __nv_bfloat16* Bh = Al + 128 * 48;
        const __nv_bfloat16* Bl = Bh + 32 * 80;

#pragma unroll
        for (int kk = 0; kk < 32; kk += 16) {
            wmma::fragment<wmma::matrix_a, 16, 16, 16, __nv_bfloat16, wmma::row_major> ah[2], al[2];
            wmma::fragment<wmma::matrix_b, 16, 16, 16, __nv_bfloat16, wmma::row_major> bh[2], bl[2];
#pragma unroll
            for (int i = 0; i < 2; i++) {
                wmma::load_matrix_sync(ah[i], Ah + (wm * 32 + i * 16) * 48 + kk, 48);
                wmma::load_matrix_sync(al[i], Al + (wm * 32 + i * 16) * 48 + kk, 48);
            }
#pragma unroll
            for (int j = 0; j < 2; j++) {
                wmma::load_matrix_sync(bh[j], Bh + kk * 80 + wn * 32 + j * 16, 80);
                wmma::load_matrix_sync(bl[j], Bl + kk * 80 + wn * 32 + j * 16, 80);
            }
#pragma unroll
            for (int i = 0; i < 2; i++)
#pragma unroll
                for (int j = 0; j < 2; j++) {
                    wmma::mma_sync(acc[i][j], ah[i], bh[j], acc[i][j]);
                    wmma::mma_sync(acc[i][j], al[i], bh[j], acc[i][j]);
                    wmma::mma_sync(acc[i][j], ah[i], bl[j], acc[i][j]);
                }
        }

        if (it < 31) storeStage(cur ^ 1);       // stage cur^1 fully consumed in iter it-1
        __syncthreads();
    }

    // store: each 16-row tile lies entirely in feat- or feat_a-half (20000 % 16 == 0)
#pragma unroll
    for (int i = 0; i < 2; i++) {
        int gr = bm0 + wm * 32 + i * 16;
        float* dst = (gr < NROWS) ? (g_z0 + (size_t)gr * OUTF)
                                  : (g_za0 + (size_t)(gr - NROWS) * OUTF);
#pragma unroll
        for (int j = 0; j < 2; j++)
            wmma::store_matrix_sync(dst + wn * 32 + j * 16, acc[i][j], OUTF, wmma::mem_row_major);
    }
}

// ---------------------------------------------------------------------------
// Fused GEMM23 v2: one block per 64-row M-tile, loops over all 16 N-tiles.
//   A tiles (z0, z2) loaded + bf16-split ONCE per block (16x less convert work).
//   B tiles register-prefetched per N-iter into a single smem stage.
//   phase 0: z0 @ W2 -> mean = clip(__expf), disp = clip(softplus fast)
//   phase 1: z2 @ W2 -> h
// 128 threads, warp tile 32x32. Dynamic smem 63488 B.
// ---------------------------------------------------------------------------
__global__ void __launch_bounds__(128) gemm23_kernel(const float* __restrict__ W2,
                                                     float* __restrict__ out_h,
                                                     float* __restrict__ out_mean,
                                                     float* __restrict__ out_disp) {
    extern __shared__ char smemRaw[];
    __nv_bfloat16* sA1h = reinterpret_cast<__nv_bfloat16*>(smemRaw);      // [64][72]
    __nv_bfloat16* sA1l = sA1h + 64 * 72;
    __nv_bfloat16* sA2h = sA1l + 64 * 72;
    __nv_bfloat16* sA2l = sA2h + 64 * 72;
    __nv_bfloat16* sBh  = sA2l + 64 * 72;                                 // [64][80]
    __nv_bfloat16* sBl  = sBh + 64 * 80;
    float*         sStage = reinterpret_cast<float*>(sBl + 64 * 80);      // [4][16][24]

    const int tid  = threadIdx.x;
    const int lane = tid & 31;
    const int warp = tid >> 5;
    const int wm   = warp & 1;
    const int wn   = warp >> 1;
    const int bm0  = blockIdx.x * 64;

    // A tiles: 64 x 64 fp32 from g_z0 and g_z2, split once (8 float4/thread each)
#pragma unroll
    for (int it = 0; it < 8; it++) {
        int idx = tid + it * 128;
        int r   = idx >> 4;
        int c   = (idx & 15) * 4;
        int gr  = bm0 + r;
        float4 v1 = make_float4(0.f, 0.f, 0.f, 0.f);
        float4 v2 = v1;
        if (gr < NROWS) {
            v1 = *reinterpret_cast<const float4*>(g_z0 + (size_t)gr * OUTF + c);
            v2 = *reinterpret_cast<const float4*>(g_z2 + (size_t)gr * OUTF + c);
        }
        split_store_f4(&sA1h[r * 72 + c], &sA1l[r * 72 + c], v1);
        split_store_f4(&sA2h[r * 72 + c], &sA2l[r * 72 + c], v2);
    }

    float4 bReg[8];
    auto prefetchB = [&](int bn0) {
#pragma unroll
        for (int it = 0; it < 8; it++) {
            int idx = tid + it * 128;
            int r   = idx >> 4;
            int c   = (idx & 15) * 4;
            bReg[it] = *reinterpret_cast<const float4*>(W2 + (size_t)r * INF + bn0 + c);
        }
    };

    prefetchB(0);
    __syncthreads();   // A tiles visible

#pragma unroll 1
    for (int nt = 0; nt < 16; nt++) {
        // commit prefetched B tile to smem
#pragma unroll
        for (int it = 0; it < 8; it++) {
            int idx = tid + it * 128;
            int r   = idx >> 4;
            int c   = (idx & 15) * 4;
            split_store_f4(&sBh[r * 80 + c], &sBl[r * 80 + c], bReg[it]);
        }
        __syncthreads();
        if (nt < 15) prefetchB((nt + 1) * 64);   // overlap next B load with MMAs

        wmma::fragment<wmma::accumulator, 16, 16, 16, float> acc0[2][2], acc1[2][2];
#pragma unroll
        for (int i = 0; i < 2; i++)
#pragma unroll
            for (int j = 0; j < 2; j++) {
                wmma::fill_fragment(acc0[i][j], 0.0f);
                wmma::fill_fragment(acc1[i][j], 0.0f);
            }

#pragma unroll
        for (int kk = 0; kk < 64; kk += 16) {
            wmma::fragment<wmma::matrix_b, 16, 16, 16, __nv_bfloat16, wmma::row_major> bh[2], bl[2];
#pragma unroll
            for (int j = 0; j < 2; j++) {
                wmma::load_matrix_sync(bh[j], sBh + kk * 80 + wn * 32 + j * 16, 80);
                wmma::load_matrix_sync(bl[j], sBl + kk * 80 + wn * 32 + j * 16, 80);
            }
            wmma::fragment<wmma::matrix_a, 16, 16, 16, __nv_bfloat16, wmma::row_major> ah[2], al[2];
            // phase 0: z0
#pragma unroll
            for (int i = 0; i < 2; i++) {
                wmma::load_matrix_sync(ah[i], sA1h + (wm * 32 + i * 16) * 72 + kk, 72);
                wmma::load_matrix_sync(al[i], sA1l + (wm * 32 + i * 16) * 72 + kk, 72);
            }
#pragma unroll
            for (int i = 0; i < 2; i++)
#pragma unroll
                for (int j = 0; j < 2; j++) {
                    wmma::mma_sync(acc0[i][j], ah[i], bh[j], acc0[i][j]);
                    wmma::mma_sync(acc0[i][j], al[i], bh[j], acc0[i][j]);
                    wmma::mma_sync(acc0[i][j], ah[i], bl[j], acc0[i][j]);
                }
            // phase 1: z2
#pragma unroll
            for (int i = 0; i < 2; i++) {
                wmma::load_matrix_sync(ah[i], sA2h + (wm * 32 + i * 16) * 72 + kk, 72);
                wmma::load_matrix_sync(al[i], sA2l + (wm * 32 + i * 16) * 72 + kk, 72);
            }
#pragma unroll
            for (int i = 0; i < 2; i++)
#pragma unroll
                for (int j = 0; j < 2; j++) {
                    wmma::mma_sync(acc1[i][j], ah[i], bh[j], acc1[i][j]);
                    wmma::mma_sync(acc1[i][j], al[i], bh[j], acc1[i][j]);
                    wmma::mma_sync(acc1[i][j], ah[i], bl[j], acc1[i][j]);
                }
        }

        // epilogue
        const int bn0 = nt * 64;
#pragma unroll
        for (int i = 0; i < 2; i++) {
            int gr = bm0 + wm * 32 + i * 16;
            if (gr >= NROWS) continue;
#pragma unroll
            for (int j = 0; j < 2; j++) {
                int gc = bn0 + wn * 32 + j * 16;
                // h: direct store
                wmma::store_matrix_sync(out_h + (size_t)gr * INF + gc, acc1[i][j], INF,
                                        wmma::mem_row_major);
                // mean/disp: stage -> fast-math -> float4 stores
                float* st = sStage + warp * 16 * 24;
                wmma::store_matrix_sync(st, acc0[i][j], 24, wmma::mem_row_major);
                __syncwarp();
#pragma unroll
                for (int t = 0; t < 2; t++) {
                    int idx = lane + t * 32;         // 0..63 float4s
                    int rr  = idx >> 2;
                    int cc  = (idx & 3) * 4;
                    float4 x = *reinterpret_cast<const float4*>(st + rr * 24 + cc);
                    float4 m, sp;
                    m.x = fminf(fmaxf(__expf(x.x), 1e-5f), 1e6f);
                    m.y = fminf(fmaxf(__expf(x.y), 1e-5f), 1e6f);
                    m.z = fminf(fmaxf(__expf(x.z), 1e-5f), 1e6f);
                    m.w = fminf(fmaxf(__expf(x.w), 1e-5f), 1e6f);
                    sp.x = fmaxf(x.x, 0.f) + __logf(1.f + __expf(-fabsf(x.x)));
                    sp.y = fmaxf(x.y, 0.f) + __logf(1.f + __expf(-fabsf(x.y)));
                    sp.z = fmaxf(x.z, 0.f) + __logf(1.f + __expf(-fabsf(x.z)));
                    sp.w = fmaxf(x.w, 0.f) + __logf(1.f + __expf(-fabsf(x.w)));
                    sp.x = fminf(fmaxf(sp.x, 1e-4f), 1e4f);
                    sp.y = fminf(fmaxf(sp.y, 1e-4f), 1e4f);
                    sp.z = fminf(fmaxf(sp.z, 1e-4f), 1e4f);
                    sp.w = fminf(fmaxf(sp.w, 1e-4f), 1e4f);
                    size_t o = (size_t)(gr + rr) * INF + gc + cc;
                    *reinterpret_cast<float4*>(out_mean + o) = m;
                    *reinterpret_cast<float4*>(out_disp + o) = sp;
                }
                __syncwarp();
            }
        }
        __syncthreads();   // protect sBh/sBl before next commit
    }
}

// ---------------------------------------------------------------------------
// Fused SpMM for the three independent scatters:
//   A-edges  (t in [0,nnz)):   z  += v * z0[col]   AND   sa += v * za0[col]
//   Aa-edges (t in [nnz,nnz+nnz_a)):                    ss += v * za0[col_a]
// Half-warp (16 lanes) per edge, one float4 vector atomic per lane per output.
// ---------------------------------------------------------------------------
__global__ void __launch_bounds__(256) spmm3_kernel(const int* __restrict__ row,
                                                    const int* __restrict__ col,
                                                    const float* __restrict__ vals,
                                                    const int* __restrict__ row_a,
                                                    const int* __restrict__ col_a,
                                                    const float* __restrict__ vals_a,
                                                    float* __restrict__ z_out,
                                                    int nnz, int nnz_a) {
    long gid = (long)blockIdx.x * 256 + threadIdx.x;
    long t   = gid >> 4;
    int  j   = (int)(gid & 15) * 4;

    if (t < nnz) {
        int   c = __ldg(col + t);
        int   r = __ldg(row + t);
        float v = __ldg(vals + t);
        float4 x0 = *reinterpret_cast<const float4*>(g_z0 + (size_t)c * OUTF + j);
        atomicAdd(reinterpret_cast<float4*>(z_out + (size_t)r * OUTF + j),
                  make_float4(x0.x * v, x0.y * v, x0.z * v, x0.w * v));
        float4 xa = *reinterpret_cast<const float4*>(g_za0 + (size_t)c * OUTF + j);
        atomicAdd(reinterpret_cast<float4*>(g_sa + (size_t)r * OUTF + j),
                  make_float4(xa.x * v, xa.y * v, xa.z * v, xa.w * v));
    } else {
        long e = t - nnz;
        if (e < nnz_a) {
            int   c = __ldg(col_a + e);
            int   r = __ldg(row_a + e);
            float v = __ldg(vals_a + e);
            float4 xa = *reinterpret_cast<const float4*>(g_za0 + (size_t)c * OUTF + j);
            atomicAdd(reinterpret_cast<float4*>(g_ss + (size_t)r * OUTF + j),
                      make_float4(xa.x * v, xa.y * v, xa.z * v, xa.w * v));
        }
    }
}

// ---------------------------------------------------------------------------
// SpMM4: z2 += vals[e] * z[col[e]]   (z lives in d_out)
// ---------------------------------------------------------------------------
__global__ void __launch_bounds__(256) spmm4_kernel(const int* __restrict__ row,
                                                    const int* __restrict__ col,
                                                    const float* __restrict__ vals,
                                                    const float* __restrict__ z_in,
                                                    int nnz) {
    long gid = (long)blockIdx.x * 256 + threadIdx.x;
    long e   = gid >> 4;
    int  j   = (int)(gid & 15) * 4;
    if (e >= nnz) return;

    int   c = __ldg(col + e);
    int   r = __ldg(row + e);
    float v = __ldg(vals + e);
    float4 x = *reinterpret_cast<const float4*>(z_in + (size_t)c * OUTF + j);
    atomicAdd(reinterpret_cast<float4*>(g_z2 + (size_t)r * OUTF + j),
              make_float4(x.x * v, x.y * v, x.z * v, x.w * v));
}

// ---------------------------------------------------------------------------
// Discriminator: ret[n]   = relu(sa[n])^T W relu(z[n])   + b
//                ret_a[n] = relu(ss[n])^T W relu(sa[n])  + b
// ---------------------------------------------------------------------------
__global__ void __launch_bounds__(256) disc_kernel(const float* __restrict__ z,
                                                   const float* __restrict__ dW,
                                                   const float* __restrict__ db,
                                                   float* __restrict__ ret,
                                                   float* __restrict__ ret_a) {
    __shared__ float sW[64][65];
    __shared__ float sV[8][3][64];

    const int tid  = threadIdx.x;
    const int lane = tid & 31;
    const int warp = tid >> 5;

    for (int i = tid; i < 64 * 64; i += 256) sW[i >> 6][i & 63] = dW[i];
    __syncthreads();
    const float b = __ldg(db);

    for (int n = blockIdx.x * 8 + warp; n < NROWS; n += gridDim.x * 8) {
#pragma unroll
        for (int t = lane; t < 64; t += 32) {
            size_t o = (size_t)n * OUTF + t;
            sV[warp][0][t] = fmaxf(z[o], 0.f);      // emb
            sV[warp][1][t] = fmaxf(g_sa[o], 0.f);   // emb_a
            sV[warp][2][t] = fmaxf(g_ss[o], 0.f);   // emb_s
        }
        __syncwarp();

        float acc1 = 0.f, acc2 = 0.f;
#pragma unroll
        for (int kb = 0; kb < 2; kb++) {
            int k = lane + kb * 32;
            float t1 = 0.f, t2 = 0.f;
#pragma unroll 16
            for (int d = 0; d < 64; d++) {
                float w = sW[d][k];
                t1 = fmaf(sV[warp][1][d], w, t1);   // sum_d emb_a[d] W[d][k]
                t2 = fmaf(sV[warp][2][d], w, t2);   // sum_d emb_s[d] W[d][k]
            }
            acc1 = fmaf(sV[warp][0][k], t1, acc1);  // * emb[k]
            acc2 = fmaf(sV[warp][1][k], t2, acc2);  // * emb_a[k]
        }
#pragma unroll
        for (int o = 16; o; o >>= 1) {
            acc1 += __shfl_xor_sync(0xffffffffu, acc1, o);
            acc2 += __shfl_xor_sync(0xffffffffu, acc2, o);
        }
        if (lane == 0) {
            ret[n]   = acc1 + b;
            ret_a[n] = acc2 + b;
        }
        __syncwarp();
    }
}

// ---------------------------------------------------------------------------
// kernel_launch
// Output layout (flattened tuple): hiden_emb[N,64] | h[N,1024] | ret[N,1] |
//                                  ret_a[N,1] | mean[N,1024] | disp[N,1024]
// ---------------------------------------------------------------------------
extern "C" void kernel_launch(void* const* d_in, const int* in_sizes, int n_in,
                              void* d_out, int out_size) {
    const float* feat   = (const float*)d_in[0];
    const float* feat_a = (const float*)d_in[1];
    const int*   row    = (const int*)d_in[2];
    const int*   col    = (const int*)d_in[3];
    const float* vals   = (const float*)d_in[4];
    const int*   row_a  = (const int*)d_in[5];
    const int*   col_a  = (const int*)d_in[6];
    const float* vals_a = (const float*)d_in[7];
    const float* W1     = (const float*)d_in[8];
    const float* W2     = (const float*)d_in[9];
    const float* dW     = (const float*)d_in[10];
    const float* db     = (const float*)d_in[11];

    float* out   = (float*)d_out;
    float* z_out = out;                                 // hiden_emb (= z, scattered here)
    float* h_out = z_out + (size_t)NROWS * OUTF;
    float* ret   = h_out + (size_t)NROWS * INF;
    float* ret_a = ret + NROWS;
    float* mean  = ret_a + NROWS;
    float* disp  = mean + (size_t)NROWS * INF;

    const int nnz   = in_sizes[2];
    const int nnz_a = in_sizes[5];

    const int zero_blocks  = ((NROWS * OUTF) / 4 + 255) / 256;
    const int spmm3_blocks = (int)((((long)nnz + nnz_a) * 16 + 255) / 256);
    const int spmm4_blocks = (int)(((long)nnz * 16 + 255) / 256);
    const int g1_blocks    = (2 * NROWS + 127) / 128;   // 313
    const int g23_blocks   = (NROWS + 63) / 64;         // 313

    const int g1Smem  = 2 * G1_STAGE_ELEMS * 2;                               // 69632 B
    const int g23Smem = (4 * 64 * 72 + 2 * 64 * 80) * 2 + 4 * 16 * 24 * 4;    // 63488 B
    cudaFuncSetAttribute(gemm1_kernel,
                         cudaFuncAttributeMaxDynamicSharedMemorySize, g1Smem);
    cudaFuncSetAttribute(gemm23_kernel,
                         cudaFuncAttributeMaxDynamicSharedMemorySize, g23Smem);

    // 1. zero atomic-scatter destinations (z region of d_out, sa, ss, z2)
    zero_kernel<<<zero_blocks, 256>>>(z_out);
    // 2. z0 = feat @ W1 ; za0 = feat_a @ W1  (double-buffered bf16x3 GEMM)
    gemm1_kernel<<<g1_blocks, 256, g1Smem>>>(feat, feat_a, W1);
    // 3. fused scatters: z = A z0 -> d_out ; sa = A za0 ; ss = Aa za0
    spmm3_kernel<<<spmm3_blocks, 256>>>(row, col, vals, row_a, col_a, vals_a,
                                        z_out, nnz, nnz_a);
    // 4. z2 = A z  (uses z in d_out)
    spmm4_kernel<<<spmm4_blocks, 256>>>(row, col, vals, z_out, nnz);
    // 5. fused GEMM: mean/disp = f(z0 @ W2)  and  h = z2 @ W2 (= A(zW2))
    gemm23_kernel<<<g23_blocks, 128, g23Smem>>>(W2, h_out, mean, disp);
    // 6. bilinear discriminator heads
    disc_kernel<<<296, 256>>>(z_out, dW, db, ret, ret_a);
}

// round 14
// speedup vs baseline: 1.1860x; 1.1860x over previous
#include <cuda_runtime.h>
#include <cuda_bf16.h>
#include <mma.h>
#include <math.h>

using namespace nvcuda;

// Problem constants (fixed by the dataset)
#define NROWS 20000
#define INF   1024
#define OUTF  64

// ---------------------------------------------------------------------------
// Scratch (device globals; no runtime allocation allowed)
// ---------------------------------------------------------------------------
__device__ alignas(256) float g_z0 [NROWS * OUTF];          // feat   @ W1
__device__ alignas(256) float g_za0[20064 * OUTF];          // feat_a @ W1 (padded: gemm1 tail rows)
__device__ alignas(256) float g_z2 [NROWS * OUTF];          // spmm(A, z)
__device__ alignas(256) float g_sa [NROWS * OUTF];          // spmm(A,  za0)
__device__ alignas(256) float g_ss [NROWS * OUTF];          // spmm(Aa, za0)

// ---------------------------------------------------------------------------
// fp32 -> bf16 hi/lo split helpers (error-compensated tensor-core GEMM)
// ---------------------------------------------------------------------------
__device__ __forceinline__ void split_store2(__nv_bfloat16* hiPtr, __nv_bfloat16* loPtr,
                                             float x, float y) {
    __nv_bfloat162 h = __floats2bfloat162_rn(x, y);
    *reinterpret_cast<__nv_bfloat162*>(hiPtr) = h;
    float rx = x - __bfloat162float(__low2bfloat16(h));
    float ry = y - __bfloat162float(__high2bfloat16(h));
    *reinterpret_cast<__nv_bfloat162*>(loPtr) = __floats2bfloat162_rn(rx, ry);
}

__device__ __forceinline__ void split_store_f4(__nv_bfloat16* hi, __nv_bfloat16* lo, float4 v) {
    split_store2(hi + 0, lo + 0, v.x, v.y);
    split_store2(hi + 2, lo + 2, v.z, v.w);
}

// ---------------------------------------------------------------------------
// zero scratch that receives atomic scatter (+ z region of d_out)
// ---------------------------------------------------------------------------
__global__ void __launch_bounds__(256) zero_kernel(float* __restrict__ z_out) {
    int i = blockIdx.x * 256 + threadIdx.x;            // over 320000 float4 per array
    if (i < (NROWS * OUTF) / 4) {
        float4 z = make_float4(0.f, 0.f, 0.f, 0.f);
        reinterpret_cast<float4*>(z_out)[i] = z;
        reinterpret_cast<float4*>(g_sa)[i]  = z;
        reinterpret_cast<float4*>(g_ss)[i]  = z;
        reinterpret_cast<float4*>(g_z2)[i]  = z;
    }
}

// ---------------------------------------------------------------------------
// GEMM1 (R10 config — best measured): [40000,1024] @ [1024,64] -> z0 / za0
// BM=128, BN=64, BK=32, 8 warps, warp tile 32x32, bf16x3 split MMA.
// Register-prefetch pipeline, single smem buffer (34 KB static).
// ---------------------------------------------------------------------------
__global__ void __launch_bounds__(256) gemm1_kernel(const float* __restrict__ feat,
                                                    const float* __restrict__ feat_a,
                                                    const float* __restrict__ W1) {
    __shared__ alignas(32) __nv_bfloat16 sAh[128][48];   // BK=32 (+16 pad)
    __shared__ alignas(32) __nv_bfloat16 sAl[128][48];
    __shared__ alignas(32) __nv_bfloat16 sBh[32][80];
    __shared__ alignas(32) __nv_bfloat16 sBl[32][80];

    const int tid  = threadIdx.x;
    const int warp = tid >> 5;
    const int wm   = warp & 3;   // 4 row groups of 32
    const int wn   = warp >> 2;  // 2 col groups of 32
    const int bm0  = blockIdx.x * 128;

    wmma::fragment<wmma::accumulator, 16, 16, 16, float> acc[2][2];
#pragma unroll
    for (int i = 0; i < 2; i++)
#pragma unroll
        for (int j = 0; j < 2; j++) wmma::fill_fragment(acc[i][j], 0.0f);

    float4 aReg[4];
    float4 bReg[2];

    auto prefetch = [&](int k0) {
#pragma unroll
        for (int it = 0; it < 4; it++) {
            int idx = tid + it * 256;          // 0..1023
            int r   = idx >> 3;                // 0..127
            int c   = (idx & 7) * 4;           // 0..28
            int gr  = bm0 + r;
            float4 v = make_float4(0.f, 0.f, 0.f, 0.f);
            if (gr < 2 * NROWS) {
                const float* src = (gr < NROWS) ? (feat + (size_t)gr * INF)
                                                : (feat_a + (size_t)(gr - NROWS) * INF);
                v = *reinterpret_cast<const float4*>(src + k0 + c);
            }
            aReg[it] = v;
        }
#pragma unroll
        for (int it = 0; it < 2; it++) {
            int idx = tid + it * 256;          // 0..511
            int r   = idx >> 4;                // 0..31
            int c   = (idx & 15) * 4;          // 0..60
            bReg[it] = *reinterpret_cast<const float4*>(W1 + (size_t)(k0 + r) * OUTF + c);
        }
    };

    prefetch(0);

#pragma unroll 1
    for (int k0 = 0; k0 < INF; k0 += 32) {
        // commit prefetched registers to smem (bf16 hi/lo, packed stores)
#pragma unroll
        for (int it = 0; it < 4; it++) {
            int idx = tid + it * 256;
            int r   = idx >> 3;
            int c   = (idx & 7) * 4;
            split_store_f4(&sAh[r][c], &sAl[r][c], aReg[it]);
        }
#pragma unroll
        for (int it = 0; it < 2; it++) {
            int idx = tid + it * 256;
            int r   = idx >> 4;
            int c   = (idx & 15) * 4;
            split_store_f4(&sBh[r][c], &sBl[r][c], bReg[it]);
        }
        __syncthreads();

        // issue next tile's global loads NOW (latency overlaps MMAs below)
        if (k0 + 32 < INF) prefetch(k0 + 32);

#pragma unroll
        for (int kk = 0; kk < 32; kk += 16) {
            wmma::fragment<wmma::matrix_a, 16, 16, 16, __nv_bfloat16, wmma::row_major> ah[2], al[2];
            wmma::fragment<wmma::matrix_b, 16, 16, 16, __nv_bfloat16, wmma::row_major> bh[2], bl[2];
#pragma unroll
            for (int i = 0; i < 2; i++) {
                wmma::load_matrix_sync(ah[i], &sAh[wm * 32 + i * 16][kk], 48);
                wmma::load_matrix_sync(al[i], &sAl[wm * 32 + i * 16][kk], 48);
            }
#pragma unroll
            for (int j = 0; j < 2; j++) {
                wmma::load_matrix_sync(bh[j], &sBh[kk][wn * 32 + j * 16], 80);
                wmma::load_matrix_sync(bl[j], &sBl[kk][wn * 32 + j * 16], 80);
            }
#pragma unroll
            for (int i = 0; i < 2; i++)
#pragma unroll
                for (int j = 0; j < 2; j++) {
                    wmma::mma_sync(acc[i][j], ah[i], bh[j], acc[i][j]);
                    wmma::mma_sync(acc[i][j], al[i], bh[j], acc[i][j]);
                    wmma::mma_sync(acc[i][j], ah[i], bl[j], acc[i][j]);
                }
        }
        __syncthreads();
    }

    // store: each 16-row tile lies entirely in feat- or feat_a-half (20000 % 16 == 0)
#pragma unroll
    for (int i = 0; i < 2; i++) {
        int gr = bm0 + wm * 32 + i * 16;
        float* dst = (gr < NROWS) ? (g_z0 + (size_t)gr * OUTF)
                                  : (g_za0 + (size_t)(gr - NROWS) * OUTF);
#pragma unroll
        for (int j = 0; j < 2; j++)
            wmma::store_matrix_sync(dst + wn * 32 + j * 16, acc[i][j], OUTF, wmma::mem_row_major);
    }
}

// ---------------------------------------------------------------------------
// Fused GEMM23 v3: 4 N-tiles per block (middle point of A-reuse vs parallelism).
// Grid (4, 313): blockIdx.y = 64-row M-tile, blockIdx.x = group of 4 N-tiles.
//   A tiles (z0, z2) loaded + bf16-split once per block (4x less convert/L2
//   traffic than per-N-tile blocks); B tiles register-prefetched per N-iter.
//   phase 0: z0 @ W2 -> mean = clip(__expf), disp = clip(softplus fast)
//   phase 1: z2 @ W2 -> h
// 128 threads, warp tile 32x32. Dynamic smem 63488 B.
// ---------------------------------------------------------------------------
#define NT_PER_BLOCK 4

__global__ void __launch_bounds__(128) gemm23_kernel(const float* __restrict__ W2,
                                                     float* __restrict__ out_h,
                                                     float* __restrict__ out_mean,
                                                     float* __restrict__ out_disp) {
    extern __shared__ char smemRaw[];
    __nv_bfloat16* sA1h = reinterpret_cast<__nv_bfloat16*>(smemRaw);      // [64][72]
    __nv_bfloat16* sA1l = sA1h + 64 * 72;
    __nv_bfloat16* sA2h = sA1l + 64 * 72;
    __nv_bfloat16* sA2l = sA2h + 64 * 72;
    __nv_bfloat16* sBh  = sA2l + 64 * 72;                                 // [64][80]
    __nv_bfloat16* sBl  = sBh + 64 * 80;
    float*         sStage = reinterpret_cast<float*>(sBl + 64 * 80);      // [4][16][24]

    const int tid  = threadIdx.x;
    const int lane = tid & 31;
    const int warp = tid >> 5;
    const int wm   = warp & 1;
    const int wn   = warp >> 1;
    const int bm0  = blockIdx.y * 64;
    const int nt0  = blockIdx.x * NT_PER_BLOCK;

    // A tiles: 64 x 64 fp32 from g_z0 and g_z2, split once (8 float4/thread each)
#pragma unroll
    for (int it = 0; it < 8; it++) {
        int idx = tid + it * 128;
        int r   = idx >> 4;
        int c   = (idx & 15) * 4;
        int gr  = bm0 + r;
        float4 v1 = make_float4(0.f, 0.f, 0.f, 0.f);
        float4 v2 = v1;
        if (gr < NROWS) {
            v1 = *reinterpret_cast<const float4*>(g_z0 + (size_t)gr * OUTF + c);
            v2 = *reinterpret_cast<const float4*>(g_z2 + (size_t)gr * OUTF + c);
        }
        split_store_f4(&sA1h[r * 72 + c], &sA1l[r * 72 + c], v1);
        split_store_f4(&sA2h[r * 72 + c], &sA2l[r * 72 + c], v2);
    }

    float4 bReg[8];
    auto prefetchB = [&](int bn0) {
#pragma unroll
        for (int it = 0; it < 8; it++) {
            int idx = tid + it * 128;
            int r   = idx >> 4;
            int c   = (idx & 15) * 4;
            bReg[it] = *reinterpret_cast<const float4*>(W2 + (size_t)r * INF + bn0 + c);
        }
    };

    prefetchB(nt0 * 64);
    __syncthreads();   // A tiles visible

#pragma unroll 1
    for (int t = 0; t < NT_PER_BLOCK; t++) {
        const int bn0 = (nt0 + t) * 64;
        // commit prefetched B tile to smem
#pragma unroll
        for (int it = 0; it < 8; it++) {
            int idx = tid + it * 128;
            int r   = idx >> 4;
            int c   = (idx & 15) * 4;
            split_store_f4(&sBh[r * 80 + c], &sBl[r * 80 + c], bReg[it]);
        }
        __syncthreads();
        if (t + 1 < NT_PER_BLOCK) prefetchB((nt0 + t + 1) * 64);  // overlap next B load

        wmma::fragment<wmma::accumulator, 16, 16, 16, float> acc0[2][2], acc1[2][2];
#pragma unroll
        for (int i = 0; i < 2; i++)
#pragma unroll
            for (int j = 0; j < 2; j++) {
                wmma::fill_fragment(acc0[i][j], 0.0f);
                wmma::fill_fragment(acc1[i][j], 0.0f);
            }

#pragma unroll
        for (int kk = 0; kk < 64; kk += 16) {
            wmma::fragment<wmma::matrix_b, 16, 16, 16, __nv_bfloat16, wmma::row_major> bh[2], bl[2];
#pragma unroll
            for (int j = 0; j < 2; j++) {
                wmma::load_matrix_sync(bh[j], sBh + kk * 80 + wn * 32 + j * 16, 80);
                wmma::load_matrix_sync(bl[j], sBl + kk * 80 + wn * 32 + j * 16, 80);
            }
            wmma::fragment<wmma::matrix_a, 16, 16, 16, __nv_bfloat16, wmma::row_major> ah[2], al[2];
            // phase 0: z0
#pragma unroll
            for (int i = 0; i < 2; i++) {
                wmma::load_matrix_sync(ah[i], sA1h + (wm * 32 + i * 16) * 72 + kk, 72);
                wmma::load_matrix_sync(al[i], sA1l + (wm * 32 + i * 16) * 72 + kk, 72);
            }
#pragma unroll
            for (int i = 0; i < 2; i++)
#pragma unroll
                for (int j = 0; j < 2; j++) {
                    wmma::mma_sync(acc0[i][j], ah[i], bh[j], acc0[i][j]);
                    wmma::mma_sync(acc0[i][j], al[i], bh[j], acc0[i][j]);
                    wmma::mma_sync(acc0[i][j], ah[i], bl[j], acc0[i][j]);
                }
            // phase 1: z2
#pragma unroll
            for (int i = 0; i < 2; i++) {
                wmma::load_matrix_sync(ah[i], sA2h + (wm * 32 + i * 16) * 72 + kk, 72);
                wmma::load_matrix_sync(al[i], sA2l + (wm * 32 + i * 16) * 72 + kk, 72);
            }
#pragma unroll
            for (int i = 0; i < 2; i++)
#pragma unroll
                for (int j = 0; j < 2; j++) {
                    wmma::mma_sync(acc1[i][j], ah[i], bh[j], acc1[i][j]);
                    wmma::mma_sync(acc1[i][j], al[i], bh[j], acc1[i][j]);
                    wmma::mma_sync(acc1[i][j], ah[i], bl[j], acc1[i][j]);
                }
        }

        // epilogue
#pragma unroll
        for (int i = 0; i < 2; i++) {
            int gr = bm0 + wm * 32 + i * 16;
            if (gr >= NROWS) continue;
#pragma unroll
            for (int j = 0; j < 2; j++) {
                int gc = bn0 + wn * 32 + j * 16;
                // h: direct store
                wmma::store_matrix_sync(out_h + (size_t)gr * INF + gc, acc1[i][j], INF,
                                        wmma::mem_row_major);
                // mean/disp: stage -> fast-math -> float4 stores
                float* st = sStage + warp * 16 * 24;
                wmma::store_matrix_sync(st, acc0[i][j], 24, wmma::mem_row_major);
                __syncwarp();
#pragma unroll
                for (int u = 0; u < 2; u++) {
                    int idx = lane + u * 32;         // 0..63 float4s
                    int rr  = idx >> 2;
                    int cc  = (idx & 3) * 4;
                    float4 x = *reinterpret_cast<const float4*>(st + rr * 24 + cc);
                    float4 m, sp;
                    m.x = fminf(fmaxf(__expf(x.x), 1e-5f), 1e6f);
                    m.y = fminf(fmaxf(__expf(x.y), 1e-5f), 1e6f);
                    m.z = fminf(fmaxf(__expf(x.z), 1e-5f), 1e6f);
                    m.w = fminf(fmaxf(__expf(x.w), 1e-5f), 1e6f);
                    sp.x = fmaxf(x.x, 0.f) + __logf(1.f + __expf(-fabsf(x.x)));
                    sp.y = fmaxf(x.y, 0.f) + __logf(1.f + __expf(-fabsf(x.y)));
                    sp.z = fmaxf(x.z, 0.f) + __logf(1.f + __expf(-fabsf(x.z)));
                    sp.w = fmaxf(x.w, 0.f) + __logf(1.f + __expf(-fabsf(x.w)));
                    sp.x = fminf(fmaxf(sp.x, 1e-4f), 1e4f);
                    sp.y = fminf(fmaxf(sp.y, 1e-4f), 1e4f);
                    sp.z = fminf(fmaxf(sp.z, 1e-4f), 1e4f);
                    sp.w = fminf(fmaxf(sp.w, 1e-4f), 1e4f);
                    size_t o = (size_t)(gr + rr) * INF + gc + cc;
                    *reinterpret_cast<float4*>(out_mean + o) = m;
                    *reinterpret_cast<float4*>(out_disp + o) = sp;
                }
                __syncwarp();
            }
        }
        __syncthreads();   // protect sBh/sBl before next commit
    }
}

// ---------------------------------------------------------------------------
// Fused SpMM for the three independent scatters:
//   A-edges  (t in [0,nnz)):   z  += v * z0[col]   AND   sa += v * za0[col]
//   Aa-edges (t in [nnz,nnz+nnz_a)):                    ss += v * za0[col_a]
// Half-warp (16 lanes) per edge, one float4 vector atomic per lane per output.
// ---------------------------------------------------------------------------
__global__ void __launch_bounds__(256) spmm3_kernel(const int* __restrict__ row,
                                                    const int* __restrict__ col,
                                                    const float* __restrict__ vals,
                                                    const int* __restrict__ row_a,
                                                    const int* __restrict__ col_a,
                                                    const float* __restrict__ vals_a,
                                                    float* __restrict__ z_out,
                                                    int nnz, int nnz_a) {
    long gid = (long)blockIdx.x * 256 + threadIdx.x;
    long t   = gid >> 4;
    int  j   = (int)(gid & 15) * 4;

    if (t < nnz) {
        int   c = __ldg(col + t);
        int   r = __ldg(row + t);
        float v = __ldg(vals + t);
        float4 x0 = *reinterpret_cast<const float4*>(g_z0 + (size_t)c * OUTF + j);
        atomicAdd(reinterpret_cast<float4*>(z_out + (size_t)r * OUTF + j),
                  make_float4(x0.x * v, x0.y * v, x0.z * v, x0.w * v));
        float4 xa = *reinterpret_cast<const float4*>(g_za0 + (size_t)c * OUTF + j);
        atomicAdd(reinterpret_cast<float4*>(g_sa + (size_t)r * OUTF + j),
                  make_float4(xa.x * v, xa.y * v, xa.z * v, xa.w * v));
    } else {
        long e = t - nnz;
        if (e < nnz_a) {
            int   c = __ldg(col_a + e);
            int   r = __ldg(row_a + e);
            float v = __ldg(vals_a + e);
            float4 xa = *reinterpret_cast<const float4*>(g_za0 + (size_t)c * OUTF + j);
            atomicAdd(reinterpret_cast<float4*>(g_ss + (size_t)r * OUTF + j),
                      make_float4(xa.x * v, xa.y * v, xa.z * v, xa.w * v));
        }
    }
}

// ---------------------------------------------------------------------------
// SpMM4: z2 += vals[e] * z[col[e]]   (z lives in d_out)
// ---------------------------------------------------------------------------
__global__ void __launch_bounds__(256) spmm4_kernel(const int* __restrict__ row,
                                                    const int* __restrict__ col,
                                                    const float* __restrict__ vals,
                                                    const float* __restrict__ z_in,
                                                    int nnz) {
    long gid = (long)blockIdx.x * 256 + threadIdx.x;
    long e   = gid >> 4;
    int  j   = (int)(gid & 15) * 4;
    if (e >= nnz) return;

    int   c = __ldg(col + e);
    int   r = __ldg(row + e);
    float v = __ldg(vals + e);
    float4 x = *reinterpret_cast<const float4*>(z_in + (size_t)c * OUTF + j);
    atomicAdd(reinterpret_cast<float4*>(g_z2 + (size_t)r * OUTF + j),
              make_float4(x.x * v, x.y * v, x.z * v, x.w * v));
}

// ---------------------------------------------------------------------------
// Discriminator: ret[n]   = relu(sa[n])^T W relu(z[n])   + b
//                ret_a[n] = relu(ss[n])^T W relu(sa[n])  + b
// ---------------------------------------------------------------------------
__global__ void __launch_bounds__(256) disc_kernel(const float* __restrict__ z,
                                                   const float* __restrict__ dW,
                                                   const float* __restrict__ db,
                                                   float* __restrict__ ret,
                                                   float* __restrict__ ret_a) {
    __shared__ float sW[64][65];
    __shared__ float sV[8][3][64];

    const int tid  = threadIdx.x;
    const int lane = tid & 31;
    const int warp = tid >> 5;

    for (int i = tid; i < 64 * 64; i += 256) sW[i >> 6][i & 63] = dW[i];
    __syncthreads();
    const float b = __ldg(db);

    for (int n = blockIdx.x * 8 + warp; n < NROWS; n += gridDim.x * 8) {
#pragma unroll
        for (int t = lane; t < 64; t += 32) {
            size_t o = (size_t)n * OUTF + t;
            sV[warp][0][t] = fmaxf(z[o], 0.f);      // emb
            sV[warp][1][t] = fmaxf(g_sa[o], 0.f);   // emb_a
            sV[warp][2][t] = fmaxf(g_ss[o], 0.f);   // emb_s
        }
        __syncwarp();

        float acc1 = 0.f, acc2 = 0.f;
#pragma unroll
        for (int kb = 0; kb < 2; kb++) {
            int k = lane + kb * 32;
            float t1 = 0.f, t2 = 0.f;
#pragma unroll 16
            for (int d = 0; d < 64; d++) {
                float w = sW[d][k];
                t1 = fmaf(sV[warp][1][d], w, t1);   // sum_d emb_a[d] W[d][k]
                t2 = fmaf(sV[warp][2][d], w, t2);   // sum_d emb_s[d] W[d][k]
            }
            acc1 = fmaf(sV[warp][0][k], t1, acc1);  // * emb[k]
            acc2 = fmaf(sV[warp][1][k], t2, acc2);  // * emb_a[k]
        }
#pragma unroll
        for (int o = 16; o; o >>= 1) {
            acc1 += __shfl_xor_sync(0xffffffffu, acc1, o);
            acc2 += __shfl_xor_sync(0xffffffffu, acc2, o);
        }
        if (lane == 0) {
            ret[n]   = acc1 + b;
            ret_a[n] = acc2 + b;
        }
        __syncwarp();
    }
}

// ---------------------------------------------------------------------------
// kernel_launch
// Output layout (flattened tuple): hiden_emb[N,64] | h[N,1024] | ret[N,1] |
//                                  ret_a[N,1] | mean[N,1024] | disp[N,1024]
// ---------------------------------------------------------------------------
extern "C" void kernel_launch(void* const* d_in, const int* in_sizes, int n_in,
                              void* d_out, int out_size) {
    const float* feat   = (const float*)d_in[0];
    const float* feat_a = (const float*)d_in[1];
    const int*   row    = (const int*)d_in[2];
    const int*   col    = (const int*)d_in[3];
    const float* vals   = (const float*)d_in[4];
    const int*   row_a  = (const int*)d_in[5];
    const int*   col_a  = (const int*)d_in[6];
    const float* vals_a = (const float*)d_in[7];
    const float* W1     = (const float*)d_in[8];
    const float* W2     = (const float*)d_in[9];
    const float* dW     = (const float*)d_in[10];
    const float* db     = (const float*)d_in[11];

    float* out   = (float*)d_out;
    float* z_out = out;                                 // hiden_emb (= z, scattered here)
    float* h_out = z_out + (size_t)NROWS * OUTF;
    float* ret   = h_out + (size_t)NROWS * INF;
    float* ret_a = ret + NROWS;
    float* mean  = ret_a + NROWS;
    float* disp  = mean + (size_t)NROWS * INF;

    const int nnz   = in_sizes[2];
    const int nnz_a = in_sizes[5];

    const int zero_blocks  = ((NROWS * OUTF) / 4 + 255) / 256;
    const int spmm3_blocks = (int)((((long)nnz + nnz_a) * 16 + 255) / 256);
    const int spmm4_blocks = (int)(((long)nnz * 16 + 255) / 256);
    const int g1_blocks    = (2 * NROWS + 127) / 128;   // 313
    const int g23_m_blocks = (NROWS + 63) / 64;         // 313

    const int g23Smem = (4 * 64 * 72 + 2 * 64 * 80) * 2 + 4 * 16 * 24 * 4;    // 63488 B
    cudaFuncSetAttribute(gemm23_kernel,
                         cudaFuncAttributeMaxDynamicSharedMemorySize, g23Smem);

    // 1. zero atomic-scatter destinations (z region of d_out, sa, ss, z2)
    zero_kernel<<<zero_blocks, 256>>>(z_out);
    // 2. z0 = feat @ W1 ; za0 = feat_a @ W1  (register-prefetch bf16x3 GEMM, R10 config)
    gemm1_kernel<<<g1_blocks, 256>>>(feat, feat_a, W1);
    // 3. fused scatters: z = A z0 -> d_out ; sa = A za0 ; ss = Aa za0
    spmm3_kernel<<<spmm3_blocks, 256>>>(row, col, vals, row_a, col_a, vals_a,
                                        z_out, nnz, nnz_a);
    // 4. z2 = A z  (uses z in d_out)
    spmm4_kernel<<<spmm4_blocks, 256>>>(row, col, vals, z_out, nnz);
    // 5. fused GEMM: mean/disp = f(z0 @ W2)  and  h = z2 @ W2 (= A(zW2))
    gemm23_kernel<<<dim3(16 / NT_PER_BLOCK, g23_m_blocks), 128, g23Smem>>>(
        W2, h_out, mean, disp);
    // 6. bilinear discriminator heads
    disc_kernel<<<296, 256>>>(z_out, dW, db, ret, ret_a);
}